// round 1
// baseline (speedup 1.0000x reference)
#include <cuda_runtime.h>
#include <cuda_bf16.h>

#define MAX_NODES 100000
#define D 64
#define EPS 1e-9f

// Scratch for aggregated features (no allocations allowed -> device global)
static __device__ float g_agg[MAX_NODES * D];

// ---------------------------------------------------------------------------
// Kernel A: zero the aggregation buffer (float4 stores)
// ---------------------------------------------------------------------------
__global__ void zero_agg_kernel(int n4) {
    int i = blockIdx.x * blockDim.x + threadIdx.x;
    if (i < n4) {
        reinterpret_cast<float4*>(g_agg)[i] = make_float4(0.f, 0.f, 0.f, 0.f);
    }
}

// ---------------------------------------------------------------------------
// Kernel B: SpMM scatter.  One thread per (edge, 16B feature chunk):
//   16 threads cover one edge's 64 features with float4 loads + 4 atomics.
// ---------------------------------------------------------------------------
__global__ void spmm_scatter_kernel(const float* __restrict__ x,
                                    const float* __restrict__ edge_val,
                                    const int*   __restrict__ edge_row,
                                    const int*   __restrict__ edge_col,
                                    int E) {
    int gid = blockIdx.x * blockDim.x + threadIdx.x;
    int e = gid >> 4;
    int q = gid & 15;
    if (e >= E) return;
    int r = __ldg(edge_row + e);
    int c = __ldg(edge_col + e);
    float v = __ldg(edge_val + e);
    float4 xv = reinterpret_cast<const float4*>(x)[c * 16 + q];
    float* dst = g_agg + r * D + q * 4;
    atomicAdd(dst + 0, v * xv.x);
    atomicAdd(dst + 1, v * xv.y);
    atomicAdd(dst + 2, v * xv.z);
    atomicAdd(dst + 3, v * xv.w);
}

// ---------------------------------------------------------------------------
// Kernel C: fused dual-hop transform.
//   Warp per node. Lane owns output features j=lane and j=lane+32.
//   W kept in shared, transposed + pair-interleaved so each k-step is one
//   conflict-free LDS.64:  sW[k*64 + 2*j' + p]  where j = j' + 32*p.
//   Feature row broadcast across the warp via shfl.
// ---------------------------------------------------------------------------
__device__ __forceinline__ float2 hop_transform(const float* __restrict__ feat_row,
                                                const float* __restrict__ sW,
                                                float b_a, float b_b,
                                                float sc_a, float sc_b,
                                                float of_a, float of_b,
                                                int lane) {
    float2 xv = reinterpret_cast<const float2*>(feat_row)[lane];
    float acc_a = 0.f, acc_b = 0.f;
    const float2* sW2 = reinterpret_cast<const float2*>(sW);
    #pragma unroll
    for (int k2 = 0; k2 < 32; ++k2) {
        float xa = __shfl_sync(0xffffffffu, xv.x, k2);
        float xb = __shfl_sync(0xffffffffu, xv.y, k2);
        float2 w0 = sW2[(2 * k2 + 0) * 32 + lane];
        float2 w1 = sW2[(2 * k2 + 1) * 32 + lane];
        acc_a = fmaf(xa, w0.x, acc_a);
        acc_a = fmaf(xb, w1.x, acc_a);
        acc_b = fmaf(xa, w0.y, acc_b);
        acc_b = fmaf(xb, w1.y, acc_b);
    }
    float ha = fmaxf(acc_a + b_a, 0.f);
    float hb = fmaxf(acc_b + b_b, 0.f);
    float s = ha + hb;
    float q = ha * ha + hb * hb;
    #pragma unroll
    for (int off = 16; off; off >>= 1) {
        s += __shfl_xor_sync(0xffffffffu, s, off);
        q += __shfl_xor_sync(0xffffffffu, q, off);
    }
    float mean = s * (1.0f / 64.0f);
    float var  = q * (1.0f / 64.0f) - mean * mean + EPS;
    float rinv = rsqrtf(var);
    float ra = (ha - mean) * sc_a * rinv + of_a;
    float rb = (hb - mean) * sc_b * rinv + of_b;
    return make_float2(ra, rb);
}

__global__ __launch_bounds__(256)
void transform_kernel(const float* __restrict__ x,
                      const float* __restrict__ W0, const float* __restrict__ b0,
                      const float* __restrict__ s0, const float* __restrict__ o0,
                      const float* __restrict__ W1, const float* __restrict__ b1,
                      const float* __restrict__ s1, const float* __restrict__ o1,
                      float* __restrict__ out, int nNodes) {
    __shared__ float sW0[D * D];
    __shared__ float sW1[D * D];
    __shared__ float sPar[6 * D];   // b0,s0,o0,b1,s1,o1

    // Cooperative load of weights, transposed + pair-interleaved
    for (int idx = threadIdx.x; idx < D * D; idx += 256) {
        int j = idx >> 6;          // output feature
        int k = idx & 63;          // input feature
        int dst = k * 64 + ((j & 31) << 1) + (j >> 5);
        sW0[dst] = W0[idx];
        sW1[dst] = W1[idx];
    }
    for (int idx = threadIdx.x; idx < 6 * D; idx += 256) {
        int which = idx >> 6, t = idx & 63;
        const float* src = (which == 0) ? b0 : (which == 1) ? s0 : (which == 2) ? o0
                         : (which == 3) ? b1 : (which == 4) ? s1 : o1;
        sPar[idx] = src[t];
    }
    __syncthreads();

    int lane = threadIdx.x & 31;
    int warp = threadIdx.x >> 5;
    int node = blockIdx.x * 8 + warp;
    if (node >= nNodes) return;

    const float* pb0 = sPar;           const float* ps0 = sPar + 64;  const float* po0 = sPar + 128;
    const float* pb1 = sPar + 192;     const float* ps1 = sPar + 256; const float* po1 = sPar + 320;

    float2 r0 = hop_transform(x + (size_t)node * D, sW0,
                              pb0[lane], pb0[lane + 32],
                              ps0[lane], ps0[lane + 32],
                              po0[lane], po0[lane + 32], lane);
    float2 r1 = hop_transform(g_agg + (size_t)node * D, sW1,
                              pb1[lane], pb1[lane + 32],
                              ps1[lane], ps1[lane + 32],
                              po1[lane], po1[lane + 32], lane);

    out[(size_t)node * D + lane]      = r0.x + r1.x;
    out[(size_t)node * D + lane + 32] = r0.y + r1.y;
}

// ---------------------------------------------------------------------------
// Launch
// ---------------------------------------------------------------------------
extern "C" void kernel_launch(void* const* d_in, const int* in_sizes, int n_in,
                              void* d_out, int out_size) {
    const float* x        = (const float*)d_in[0];
    const float* edge_val = (const float*)d_in[1];
    const float* W0       = (const float*)d_in[2];
    const float* b0       = (const float*)d_in[3];
    const float* scale0   = (const float*)d_in[4];
    const float* offset0  = (const float*)d_in[5];
    const float* W1       = (const float*)d_in[6];
    const float* b1       = (const float*)d_in[7];
    const float* scale1   = (const float*)d_in[8];
    const float* offset1  = (const float*)d_in[9];
    const int*   edge_row = (const int*)d_in[10];
    const int*   edge_col = (const int*)d_in[11];
    float* out = (float*)d_out;

    int nNodes = in_sizes[0] / D;
    int E = in_sizes[1];

    // A: zero agg
    int n4 = nNodes * (D / 4);
    zero_agg_kernel<<<(n4 + 255) / 256, 256>>>(n4);

    // B: SpMM scatter
    long long tot = (long long)E * 16;
    int grid_b = (int)((tot + 255) / 256);
    spmm_scatter_kernel<<<grid_b, 256>>>(x, edge_val, edge_row, edge_col, E);

    // C: fused transform
    int grid_c = (nNodes + 7) / 8;
    transform_kernel<<<grid_c, 256>>>(x, W0, b0, scale0, offset0,
                                      W1, b1, scale1, offset1, out, nNodes);
}